// round 13
// baseline (speedup 1.0000x reference)
#include <cuda_runtime.h>
#include <cuda_fp16.h>
#include <math.h>

#define NN 2592
#define BB 128
#define LL 64
#define CC 16
#define CHO 64
#define NTILES_R 1296         // 324 n-tiles x 4 b-tiles
#define GRID_R 592            // 4 CTAs/SM x 148 SMs, guaranteed co-resident

// ---------------- scratch (device globals; no allocation) ----------------
__device__ __half g_uhatH[(size_t)NN * BB * LL]; // [n][b][l]  ~42.5 MB fp16
__device__ float g_S0[BB * LL];
__device__ float g_s1[BB * LL];
__device__ float g_s2[BB * LL];
__device__ float g_b1[NN];
__device__ float g_b2[NN];
__device__ float g_c2[NN];
__device__ float g_nrm2[(size_t)NN * BB];
__device__ float g_mx[2];
__device__ float g_den[2];
__device__ unsigned g_work[4];   // per-phase work-steal counters
__device__ unsigned g_cnt[3];    // per-barrier arrival counters
__device__ int g_phase;          // barrier release flag

struct alignas(8) h4pack { __half2 a, b; };

__device__ __forceinline__ float squashf(float s) {
    float sq = s * s;
    return s * fabsf(s) / (1.0f + sq);
}

__device__ __forceinline__ void red_add_v4(float* p, float a, float b, float c, float d) {
    asm volatile("red.global.add.v4.f32 [%0], {%1, %2, %3, %4};"
                 :: "l"(p), "f"(a), "f"(b), "f"(c), "f"(d) : "memory");
}

// ---------------- K0: zero accumulators + sync state ----------------
__global__ void kzero() {
    int i = blockIdx.x * 256 + threadIdx.x;
    if (i < BB * LL) { g_S0[i] = 0.f; g_s1[i] = 0.f; g_s2[i] = 0.f; }
    if (i < NN) { g_b1[i] = 0.f; g_b2[i] = 0.f; }
    if (i < 4) g_work[i] = 0u;
    if (i < 3) g_cnt[i] = 0u;
    if (i == 0) g_phase = 0;
}

// ---------------- K1: u_hat(fp16) + S0 + nrm2 (R6 proven body) ----------------
__global__ void __launch_bounds__(256) k1_uhat(const float* __restrict__ x,
                                               const float* __restrict__ W) {
    __shared__ float xs[CC][BB];
    __shared__ float Ws[CC][LL];
    __shared__ float ps[CC][BB + 1];

    int t = threadIdx.x;
    int n0 = blockIdx.x * 4;
    int bg = t >> 4, lq = t & 15;
    int bbase = bg * 8;

    float s_acc[8][4];
#pragma unroll
    for (int i = 0; i < 8; i++)
#pragma unroll
        for (int j = 0; j < 4; j++) s_acc[i][j] = 0.f;

#pragma unroll 1
    for (int nn = 0; nn < 4; nn++) {
        int n = n0 + nn;
        {
            int b = t & 127, half = t >> 7;
            const float4* xp = reinterpret_cast<const float4*>(x + ((size_t)b * NN + n) * CC) + half * 2;
            float4 a = xp[0], c4 = xp[1];
            int cb = half * 8;
            xs[cb + 0][b] = a.x;  xs[cb + 1][b] = a.y;  xs[cb + 2][b] = a.z;  xs[cb + 3][b] = a.w;
            xs[cb + 4][b] = c4.x; xs[cb + 5][b] = c4.y; xs[cb + 6][b] = c4.z; xs[cb + 7][b] = c4.w;
        }
        {
            int l = t & 63, cq = t >> 6;
            const float4* wp = reinterpret_cast<const float4*>(W + ((size_t)n * LL + l) * CC + cq * 4);
            float4 a = wp[0];
            Ws[cq * 4 + 0][l] = a.x; Ws[cq * 4 + 1][l] = a.y;
            Ws[cq * 4 + 2][l] = a.z; Ws[cq * 4 + 3][l] = a.w;
        }
        __syncthreads();

        float acc[8][4];
#pragma unroll
        for (int i = 0; i < 8; i++)
#pragma unroll
            for (int j = 0; j < 4; j++) acc[i][j] = 0.f;

#pragma unroll
        for (int c = 0; c < CC; c++) {
            float4 xa = *reinterpret_cast<const float4*>(&xs[c][bbase]);
            float4 xb = *reinterpret_cast<const float4*>(&xs[c][bbase + 4]);
            float4 wv = *reinterpret_cast<const float4*>(&Ws[c][lq * 4]);
            float xr[8] = {xa.x, xa.y, xa.z, xa.w, xb.x, xb.y, xb.z, xb.w};
            float wr[4] = {wv.x, wv.y, wv.z, wv.w};
#pragma unroll
            for (int i = 0; i < 8; i++)
#pragma unroll
                for (int j = 0; j < 4; j++) acc[i][j] += xr[i] * wr[j];
        }

        __half* ub = g_uhatH + (size_t)n * BB * LL;
#pragma unroll
        for (int i = 0; i < 8; i++) {
            int b = bbase + i;
            h4pack pk;
            pk.a = __floats2half2_rn(acc[i][0], acc[i][1]);
            pk.b = __floats2half2_rn(acc[i][2], acc[i][3]);
            *reinterpret_cast<h4pack*>(ub + b * LL + lq * 4) = pk;
            ps[lq][b] = acc[i][0] * acc[i][0] + acc[i][1] * acc[i][1] +
                        acc[i][2] * acc[i][2] + acc[i][3] * acc[i][3];
            s_acc[i][0] += acc[i][0]; s_acc[i][1] += acc[i][1];
            s_acc[i][2] += acc[i][2]; s_acc[i][3] += acc[i][3];
        }
        __syncthreads();
        if (t < BB) {
            float nr = 0.f;
#pragma unroll
            for (int q = 0; q < 16; q++) nr += ps[q][t];
            g_nrm2[(size_t)n * BB + t] = nr;
        }
        __syncthreads();
    }

#pragma unroll
    for (int i = 0; i < 8; i++)
        red_add_v4(&g_S0[(bbase + i) * LL + lq * 4],
                   s_acc[i][0], s_acc[i][1], s_acc[i][2], s_acc[i][3]);
}

// ---------------- kRoute: persistent A0 -> S1 -> A1 -> S2 with grid barriers ----------------
// A-phase: b[n] += (1/B) sum_b <u_hat, squash(sIn*scale)>, warp-per-n over 32 b (R6 body).
// S-phase: s[b,l] += sum_n c_n u_hat, c_n = exp(b[n]-mx)/den (R10 body).
// Barriers: threadfence + ticket; last CTA does the scalar softmax reduce (mx, den) and releases.
__global__ void __launch_bounds__(256, 4) kRoute() {
    __shared__ float vs[32 * LL];   // 8 KB (A-phase v slice)
    __shared__ float s8[8];
    __shared__ float cs[8];
    __shared__ float sred[8];
    __shared__ int s_tile;
    __shared__ unsigned s_tk;

    int t = threadIdx.x, w = t >> 5, lane = t & 31;

#pragma unroll 1
    for (int ph = 0; ph < 4; ph++) {
        if ((ph & 1) == 0) {
            // ===== A phase (ph 0: mode 0, ph 2: mode 1) =====
            int mode = ph >> 1;
            const float* sIn = mode ? g_s1 : g_S0;
            float sscale = mode ? 1.0f : (1.0f / NN);
            float* bOut = mode ? g_b2 : g_b1;

            for (;;) {
                if (t == 0) s_tile = (int)atomicAdd(&g_work[ph], 1u);
                __syncthreads();
                int tile = s_tile;
                if (tile >= NTILES_R) break;
                int nt = tile >> 2, bq = tile & 3;
                int n0 = nt * 8, b0 = bq * 32;

                for (int i = t; i < 32 * LL; i += 256)
                    vs[i] = squashf(__ldcg(&sIn[b0 * LL + i]) * sscale);
                __syncthreads();

                int n = n0 + w;
                const __half2* up = reinterpret_cast<const __half2*>(
                    g_uhatH + ((size_t)n * BB + b0) * LL) + lane;
                const float2* vp = reinterpret_cast<const float2*>(vs) + lane;
                float acc = 0.f;
#pragma unroll 8
                for (int b = 0; b < 32; b++) {
                    float2 u = __half22float2(up[b * 32]);
                    float2 vv = vp[b * 32];
                    acc += u.x * vv.x + u.y * vv.y;
                }
#pragma unroll
                for (int off = 16; off; off >>= 1) acc += __shfl_xor_sync(0xffffffffu, acc, off);
                if (lane == 0) {
                    acc *= (1.0f / BB);
                    if (mode == 1 && bq == 0) acc += __ldcg(&g_b1[n]);
                    s8[w] = acc;
                }
                __syncthreads();
                if (t == 0) {
#pragma unroll
                    for (int i = 0; i < 8; i++) atomicAdd(&bOut[n0 + i], s8[i]);
                }
                __syncthreads();   // vs/s8/s_tile reuse
            }

            // ---- grid barrier (id = ph for 0, 2 -> cnt[0], cnt[2]) + softmax reduce ----
            int bid = ph;   // 0 or 2
            if (t == 0) { __threadfence(); s_tk = atomicAdd(&g_cnt[bid == 2 ? 2 : 0], 1u); }
            __syncthreads();
            if (s_tk == GRID_R - 1) {
                __threadfence();   // acquire: all CTAs' bOut adds
                float m = -3.0e38f;
                for (int i = t; i < NN; i += 256) m = fmaxf(m, __ldcg(&bOut[i]));
#pragma unroll
                for (int off = 16; off; off >>= 1) m = fmaxf(m, __shfl_xor_sync(0xffffffffu, m, off));
                if (lane == 0) sred[w] = m;
                __syncthreads();
                float mx = sred[0];
#pragma unroll
                for (int q = 1; q < 8; q++) mx = fmaxf(mx, sred[q]);
                __syncthreads();
                float sm = 0.f;
                for (int i = t; i < NN; i += 256) sm += __expf(__ldcg(&bOut[i]) - mx);
#pragma unroll
                for (int off = 16; off; off >>= 1) sm += __shfl_xor_sync(0xffffffffu, sm, off);
                if (lane == 0) sred[w] = sm;
                __syncthreads();
                if (t == 0) {
                    g_mx[mode] = mx;
                    g_den[mode] = sred[0] + sred[1] + sred[2] + sred[3] +
                                  sred[4] + sred[5] + sred[6] + sred[7];
                    __threadfence();
                    *((volatile int*)&g_phase) = ph + 1;
                }
                __syncthreads();
            } else {
                if (t == 0) {
                    while (*((volatile int*)&g_phase) <= ph) __nanosleep(256);
                    __threadfence();
                }
                __syncthreads();
            }
        } else {
            // ===== S phase (ph 1: mode 0, ph 3: mode 1) =====
            int mode = ph >> 1;
            const float* bIn = mode ? g_b2 : g_b1;
            float* sOut = mode ? g_s2 : g_s1;
            float mx = __ldcg(&g_mx[mode]);
            float inv = 1.0f / __ldcg(&g_den[mode]);

            for (;;) {
                if (t == 0) s_tile = (int)atomicAdd(&g_work[ph], 1u);
                __syncthreads();
                int tile = s_tile;
                if (tile >= NTILES_R) break;
                int nt = tile >> 2, bq = tile & 3;
                int n0 = nt * 8, b0 = bq * 32;

                if (t < 8) {
                    float c = __expf(__ldcg(&bIn[n0 + t]) - mx) * inv;
                    cs[t] = c;
                    if (mode == 1 && bq == 0) g_c2[n0 + t] = c;
                }
                __syncthreads();

                int bl = t >> 3, l4 = t & 7;
                float a0 = 0.f, a1 = 0.f, a2 = 0.f, a3 = 0.f;
                float a4 = 0.f, a5 = 0.f, a6 = 0.f, a7 = 0.f;
#pragma unroll
                for (int nn = 0; nn < 8; nn++) {
                    float cv = cs[nn];
                    const uint4* p = reinterpret_cast<const uint4*>(
                        g_uhatH + ((size_t)(n0 + nn) * BB + b0 + bl) * LL);
                    uint4 q = p[l4];
                    float2 f0 = __half22float2(*reinterpret_cast<const __half2*>(&q.x));
                    float2 f1 = __half22float2(*reinterpret_cast<const __half2*>(&q.y));
                    float2 f2 = __half22float2(*reinterpret_cast<const __half2*>(&q.z));
                    float2 f3 = __half22float2(*reinterpret_cast<const __half2*>(&q.w));
                    a0 += cv * f0.x; a1 += cv * f0.y; a2 += cv * f1.x; a3 += cv * f1.y;
                    a4 += cv * f2.x; a5 += cv * f2.y; a6 += cv * f3.x; a7 += cv * f3.y;
                }
                float* dst = sOut + (b0 + bl) * LL + l4 * 8;
                red_add_v4(dst, a0, a1, a2, a3);
                red_add_v4(dst + 4, a4, a5, a6, a7);
                __syncthreads();   // cs/s_tile reuse
            }

            if (ph == 1) {   // plain barrier before A1
                if (t == 0) { __threadfence(); s_tk = atomicAdd(&g_cnt[1], 1u); }
                __syncthreads();
                if (s_tk == GRID_R - 1) {
                    if (t == 0) { __threadfence(); *((volatile int*)&g_phase) = 2; }
                    __syncthreads();
                } else {
                    if (t == 0) {
                        while (*((volatile int*)&g_phase) < 2) __nanosleep(256);
                        __threadfence();
                    }
                    __syncthreads();
                }
            }
            // ph == 3: fall through, kernel end is the sync
        }
    }
}

// ---------------- K6: v_j output + ConvTranspose2d ----------------
__global__ void __launch_bounds__(256) k6_out(const float* __restrict__ cw,
                                              const float* __restrict__ cb,
                                              float* __restrict__ out) {
    int t = threadIdx.x;
    if (blockIdx.x >= 2048) {
        int idx = (blockIdx.x - 2048) * 256 + t;
        out[idx] = squashf(g_s2[idx]);
        return;
    }
    int b = blockIdx.x >> 4, oh = blockIdx.x & 15;
    __shared__ float ws[32][64][2];
    __shared__ float un[32][9];
    __shared__ float bias[CHO];

    int kh = oh & 1;
    int ih = (oh + kh) >> 1;

    for (int i = t; i < 32 * 64 * 2; i += 256) {
        int ic = i >> 7, r = i & 127, oc = r >> 1, j = r & 1;
        ws[ic][oc][j] = cw[ic * 256 + oc * 4 + (1 - kh) * 2 + j];
    }
    for (int i = t; i < 288; i += 256) {
        int ic = i / 9, iw = i - ic * 9;
        int n = ic * 81 + ih * 9 + iw;
        un[ic][iw] = g_c2[n] * sqrtf(g_nrm2[(size_t)n * BB + b]);
    }
    if (t < CHO) bias[t] = cb[t];
    __syncthreads();

    int ow = t & 15, ocg = t >> 4;
    int kw = ow & 1;
    int iw = (ow + kw) >> 1;
    int j = 1 - kw;
    size_t obase = 8192 + (((size_t)b * CHO) * 16 + oh) * 16 + ow;
#pragma unroll
    for (int q = 0; q < 4; q++) {
        int oc = ocg * 4 + q;
        float acc = bias[oc];
#pragma unroll
        for (int ic = 0; ic < 32; ic++) acc += un[ic][iw] * ws[ic][oc][j];
        out[obase + (size_t)oc * 256] = acc;
    }
}

// ---------------- launch ----------------
extern "C" void kernel_launch(void* const* d_in, const int* in_sizes, int n_in,
                              void* d_out, int out_size) {
    const float* x  = (const float*)d_in[0];   // (128, 2592, 16)
    const float* W  = (const float*)d_in[1];   // (1, 2592, 1, 64, 16)
    const float* cw = (const float*)d_in[2];   // (32, 64, 2, 2)
    const float* cb = (const float*)d_in[3];   // (64,)
    float* out = (float*)d_out;                // 8192 (v_j) + 2097152 (out_img)

    kzero<<<32, 256>>>();
    k1_uhat<<<648, 256>>>(x, W);       // u_hat(fp16) + S0 + nrm2
    kRoute<<<GRID_R, 256>>>();         // A0 -> c1 -> S1 -> A1 -> c2 -> S2 (one launch)
    k6_out<<<2080, 256>>>(cw, cb, out);
}

// round 14
// speedup vs baseline: 1.1832x; 1.1832x over previous
#include <cuda_runtime.h>
#include <cuda_fp16.h>
#include <math.h>

#define NN 2592
#define BB 128
#define LL 64
#define CC 16
#define CHO 64

// ---------------- scratch (device globals; no allocation) ----------------
__device__ __half g_uhatH[(size_t)NN * BB * LL]; // [n][b][l]  ~42.5 MB fp16
__device__ float g_S0[BB * LL];                  // sum_n u_hat (exact fp32)
__device__ float g_s1[BB * LL];
__device__ float g_s2[BB * LL];
__device__ float g_b1[NN];
__device__ float g_b2[NN];
__device__ float g_c2[NN];
__device__ float g_nrm2[(size_t)NN * BB];        // [n][b] : sum_l u_hat^2 (exact fp32)

struct alignas(8) h4pack { __half2 a, b; };

__device__ __forceinline__ float squashf(float s) {
    float sq = s * s;
    return s * fabsf(s) / (1.0f + sq);   // == sq*s/((1+sq)*sqrt(sq))
}

__device__ __forceinline__ void red_add_v4(float* p, float a, float b, float c, float d) {
    asm volatile("red.global.add.v4.f32 [%0], {%1, %2, %3, %4};"
                 :: "l"(p), "f"(a), "f"(b), "f"(c), "f"(d) : "memory");
}

// ---------------- K0: zero accumulators ----------------
__global__ void kzero() {
    int i = blockIdx.x * 256 + threadIdx.x;
    if (i < BB * LL) { g_S0[i] = 0.f; g_s1[i] = 0.f; g_s2[i] = 0.f; }
    if (i < NN) { g_b1[i] = 0.f; g_b2[i] = 0.f; }
}

// ---------------- K1: u_hat(fp16) + S0 + nrm2 (R6 proven body) ----------------
__global__ void __launch_bounds__(256) k1_uhat(const float* __restrict__ x,
                                               const float* __restrict__ W) {
    __shared__ float xs[CC][BB];
    __shared__ float Ws[CC][LL];
    __shared__ float ps[CC][BB + 1];

    int t = threadIdx.x;
    int n0 = blockIdx.x * 4;
    int bg = t >> 4, lq = t & 15;
    int bbase = bg * 8;

    float s_acc[8][4];
#pragma unroll
    for (int i = 0; i < 8; i++)
#pragma unroll
        for (int j = 0; j < 4; j++) s_acc[i][j] = 0.f;

#pragma unroll 1
    for (int nn = 0; nn < 4; nn++) {
        int n = n0 + nn;
        {
            int b = t & 127, half = t >> 7;
            const float4* xp = reinterpret_cast<const float4*>(x + ((size_t)b * NN + n) * CC) + half * 2;
            float4 a = xp[0], c4 = xp[1];
            int cb = half * 8;
            xs[cb + 0][b] = a.x;  xs[cb + 1][b] = a.y;  xs[cb + 2][b] = a.z;  xs[cb + 3][b] = a.w;
            xs[cb + 4][b] = c4.x; xs[cb + 5][b] = c4.y; xs[cb + 6][b] = c4.z; xs[cb + 7][b] = c4.w;
        }
        {
            int l = t & 63, cq = t >> 6;
            const float4* wp = reinterpret_cast<const float4*>(W + ((size_t)n * LL + l) * CC + cq * 4);
            float4 a = wp[0];
            Ws[cq * 4 + 0][l] = a.x; Ws[cq * 4 + 1][l] = a.y;
            Ws[cq * 4 + 2][l] = a.z; Ws[cq * 4 + 3][l] = a.w;
        }
        __syncthreads();

        float acc[8][4];
#pragma unroll
        for (int i = 0; i < 8; i++)
#pragma unroll
            for (int j = 0; j < 4; j++) acc[i][j] = 0.f;

#pragma unroll
        for (int c = 0; c < CC; c++) {
            float4 xa = *reinterpret_cast<const float4*>(&xs[c][bbase]);
            float4 xb = *reinterpret_cast<const float4*>(&xs[c][bbase + 4]);
            float4 wv = *reinterpret_cast<const float4*>(&Ws[c][lq * 4]);
            float xr[8] = {xa.x, xa.y, xa.z, xa.w, xb.x, xb.y, xb.z, xb.w};
            float wr[4] = {wv.x, wv.y, wv.z, wv.w};
#pragma unroll
            for (int i = 0; i < 8; i++)
#pragma unroll
                for (int j = 0; j < 4; j++) acc[i][j] += xr[i] * wr[j];
        }

        __half* ub = g_uhatH + (size_t)n * BB * LL;
#pragma unroll
        for (int i = 0; i < 8; i++) {
            int b = bbase + i;
            h4pack pk;
            pk.a = __floats2half2_rn(acc[i][0], acc[i][1]);
            pk.b = __floats2half2_rn(acc[i][2], acc[i][3]);
            *reinterpret_cast<h4pack*>(ub + b * LL + lq * 4) = pk;
            ps[lq][b] = acc[i][0] * acc[i][0] + acc[i][1] * acc[i][1] +
                        acc[i][2] * acc[i][2] + acc[i][3] * acc[i][3];
            s_acc[i][0] += acc[i][0]; s_acc[i][1] += acc[i][1];
            s_acc[i][2] += acc[i][2]; s_acc[i][3] += acc[i][3];
        }
        __syncthreads();
        if (t < BB) {
            float nr = 0.f;
#pragma unroll
            for (int q = 0; q < 16; q++) nr += ps[q][t];
            g_nrm2[(size_t)n * BB + t] = nr;
        }
        __syncthreads();
    }

#pragma unroll
    for (int i = 0; i < 8; i++)
        red_add_v4(&g_S0[(bbase + i) * LL + lq * 4],
                   s_acc[i][0], s_acc[i][1], s_acc[i][2], s_acc[i][3]);
}

// ---------------- a-pass (R6 body, no tails/fences) ----------------
// grid 1296 = 324 n-tiles (8 n) x 4 b-tiles (32 b). warp w handles n0+w over 32 b.
__global__ void __launch_bounds__(256) k_apass(int mode) {
    const float* sIn = (mode == 0) ? g_S0 : g_s1;
    float sscale = (mode == 0) ? (1.0f / NN) : 1.0f;
    float* bOut = (mode == 0) ? g_b1 : g_b2;

    __shared__ float vs[32 * LL];   // 8 KB
    int t = threadIdx.x;
    int nt = blockIdx.x >> 2, bq = blockIdx.x & 3;
    int b0 = bq * 32;

    {
        const float4* sp = reinterpret_cast<const float4*>(sIn) + b0 * (LL / 4);
        float4* vp4 = reinterpret_cast<float4*>(vs);
        for (int i = t; i < 32 * LL / 4; i += 256) {
            float4 a = sp[i];
            vp4[i] = make_float4(squashf(a.x * sscale), squashf(a.y * sscale),
                                 squashf(a.z * sscale), squashf(a.w * sscale));
        }
    }
    __syncthreads();

    int w = t >> 5, lane = t & 31;
    int n = nt * 8 + w;
    const __half2* up = reinterpret_cast<const __half2*>(g_uhatH + ((size_t)n * BB + b0) * LL) + lane;
    const float2* vp = reinterpret_cast<const float2*>(vs) + lane;
    float acc = 0.f;
#pragma unroll 8
    for (int b = 0; b < 32; b++) {
        float2 u = __half22float2(up[b * 32]);
        float2 vv = vp[b * 32];
        acc += u.x * vv.x + u.y * vv.y;
    }
#pragma unroll
    for (int off = 16; off; off >>= 1) acc += __shfl_xor_sync(0xffffffffu, acc, off);
    if (lane == 0) {
        acc *= (1.0f / BB);
        if (mode == 1 && bq == 0) acc += g_b1[n];   // b2 = b1 + mean
        atomicAdd(&bOut[n], acc);
    }
}

// ---------------- s-pass: shuffle-softmax preamble + R10 clean body ----------------
// grid 1296 = 324 n-tiles (8 n) x 4 b-tiles (32 b). mode==1 bq==0 exports c2.
__global__ void __launch_bounds__(256) k_spass(int mode) {
    const float* bIn = (mode == 0) ? g_b1 : g_b2;
    float* sOut = (mode == 0) ? g_s1 : g_s2;

    __shared__ float wredA[8];
    __shared__ float wredB[8];
    __shared__ float cs[8];
    int t = threadIdx.x, lane = t & 31, wid = t >> 5;
    int nt = blockIdx.x >> 2, bq = blockIdx.x & 3;
    int n0 = nt * 8, b0 = bq * 32;

    // softmax (max then sum) with float4 loads + warp shuffles (2 barriers)
    const float4* b4 = reinterpret_cast<const float4*>(bIn);
    float m = -3.0e38f;
    for (int i = t; i < NN / 4; i += 256) {
        float4 v = b4[i];
        m = fmaxf(m, fmaxf(fmaxf(v.x, v.y), fmaxf(v.z, v.w)));
    }
#pragma unroll
    for (int off = 16; off; off >>= 1) m = fmaxf(m, __shfl_xor_sync(0xffffffffu, m, off));
    if (lane == 0) wredA[wid] = m;
    __syncthreads();
    float mx = wredA[0];
#pragma unroll
    for (int q = 1; q < 8; q++) mx = fmaxf(mx, wredA[q]);

    float sm = 0.f;
    for (int i = t; i < NN / 4; i += 256) {
        float4 v = b4[i];
        sm += __expf(v.x - mx) + __expf(v.y - mx) + __expf(v.z - mx) + __expf(v.w - mx);
    }
#pragma unroll
    for (int off = 16; off; off >>= 1) sm += __shfl_xor_sync(0xffffffffu, sm, off);
    if (lane == 0) wredB[wid] = sm;
    __syncthreads();
    float inv = 1.0f / (wredB[0] + wredB[1] + wredB[2] + wredB[3] +
                        wredB[4] + wredB[5] + wredB[6] + wredB[7]);

    if (t < 8) {
        float c = __expf(bIn[n0 + t] - mx) * inv;
        cs[t] = c;
        if (mode == 1 && bq == 0) g_c2[n0 + t] = c;
    }
    __syncthreads();

    // body: thread -> (bl = t>>3, l4 = t&7): one uint4 (8 fp16) per n
    int bl = t >> 3, l4 = t & 7;
    float a0 = 0.f, a1 = 0.f, a2 = 0.f, a3 = 0.f;
    float a4 = 0.f, a5 = 0.f, a6 = 0.f, a7 = 0.f;
#pragma unroll
    for (int nn = 0; nn < 8; nn++) {
        float cv = cs[nn];
        const uint4* p = reinterpret_cast<const uint4*>(
            g_uhatH + ((size_t)(n0 + nn) * BB + b0 + bl) * LL);
        uint4 q = p[l4];
        float2 f0 = __half22float2(*reinterpret_cast<const __half2*>(&q.x));
        float2 f1 = __half22float2(*reinterpret_cast<const __half2*>(&q.y));
        float2 f2 = __half22float2(*reinterpret_cast<const __half2*>(&q.z));
        float2 f3 = __half22float2(*reinterpret_cast<const __half2*>(&q.w));
        a0 += cv * f0.x; a1 += cv * f0.y; a2 += cv * f1.x; a3 += cv * f1.y;
        a4 += cv * f2.x; a5 += cv * f2.y; a6 += cv * f3.x; a7 += cv * f3.y;
    }
    float* dst = sOut + (b0 + bl) * LL + l4 * 8;
    red_add_v4(dst, a0, a1, a2, a3);
    red_add_v4(dst + 4, a4, a5, a6, a7);
}

// ---------------- K6 (rebuilt): one CTA per batch image + v_j blocks ----------------
// Dynamic smem: sw[4][32][64] (32KB) | sun[32][85] (10.9KB) | sout[16384] (64KB)
// thread = (quad = t>>4 : 4 oc) x (g = t&15 : parity class (ph,pw) + row-quarter qr)
// 16 positions/thread (2 oh rows x 8 ow), register acc[16][4]; coalesced float4 store.
#define K6_UP 85
#define K6_SMEM ((4 * 32 * 64 + 32 * K6_UP + 16384) * 4)
__global__ void __launch_bounds__(256) k6_out(const float* __restrict__ cw,
                                              const float* __restrict__ cb,
                                              float* __restrict__ out) {
    int t = threadIdx.x;
    if (blockIdx.x >= BB) {
        int idx = (blockIdx.x - BB) * 256 + t;   // 32*256 = 8192
        out[idx] = squashf(g_s2[idx]);
        return;
    }
    extern __shared__ float smem[];
    float* sw = smem;                    // [k][ic][oc], k = kh*2+kw
    float* sun = smem + 4 * 32 * 64;     // [ic][85]
    float* sout = sun + 32 * K6_UP;      // [oc][oh][ow] = 16384

    int b = blockIdx.x;

    // weights: sw[(k*32+ic)*64+oc] = cw[ic*256 + oc*4 + k]
    for (int i = t; i < 8192; i += 256) {
        int oc = i & 63, ic = (i >> 6) & 31, k = i >> 11;
        sw[i] = cw[ic * 256 + oc * 4 + k];
    }
    // un: n = i (= ic*81 + ih*9 + iw); sun[ic*85 + r]
    for (int i = t; i < NN; i += 256) {
        int ic = i / 81, r = i - ic * 81;
        sun[ic * K6_UP + r] = g_c2[i] * sqrtf(g_nrm2[(size_t)i * BB + b]);
    }
    __syncthreads();

    int quad = t >> 4, g = t & 15;
    int ph = (g >> 3) & 1, pw = (g >> 2) & 1, qr = g & 3;
    int kidx = (1 - ph) * 2 + (1 - pw);
    const float* swk = sw + kidx * 32 * 64 + quad * 4;
    // ih rows for ar=0,1: (2*qr+ar)+ph ; iw = e+pw
    int row0 = (2 * qr + 0 + ph) * 9 + pw;
    int row1 = (2 * qr + 1 + ph) * 9 + pw;

    float acc[16][4];
#pragma unroll
    for (int p = 0; p < 16; p++)
#pragma unroll
        for (int j = 0; j < 4; j++) acc[p][j] = 0.f;

#pragma unroll 4
    for (int ic = 0; ic < 32; ic++) {
        float4 w4 = *reinterpret_cast<const float4*>(swk + ic * 64);
        const float* ur = sun + ic * K6_UP;
#pragma unroll
        for (int e = 0; e < 8; e++) {
            float u0 = ur[row0 + e];
            float u1 = ur[row1 + e];
            acc[e][0] += u0 * w4.x; acc[e][1] += u0 * w4.y;
            acc[e][2] += u0 * w4.z; acc[e][3] += u0 * w4.w;
            acc[8 + e][0] += u1 * w4.x; acc[8 + e][1] += u1 * w4.y;
            acc[8 + e][2] += u1 * w4.z; acc[8 + e][3] += u1 * w4.w;
        }
    }

    float4 bias4 = *reinterpret_cast<const float4*>(cb + quad * 4);
    float bb[4] = {bias4.x, bias4.y, bias4.z, bias4.w};
    // sout[((quad*4+j)*16 + oh)*16 + ow], oh = 4qr+2ar+ph, ow = 2e+pw
#pragma unroll
    for (int ar = 0; ar < 2; ar++) {
        int oh = 4 * qr + 2 * ar + ph;
#pragma unroll
        for (int e = 0; e < 8; e++) {
            int ow = 2 * e + pw;
#pragma unroll
            for (int j = 0; j < 4; j++)
                sout[((quad * 4 + j) * 16 + oh) * 16 + ow] = acc[ar * 8 + e][j] + bb[j];
        }
    }
    __syncthreads();

    // coalesced store: 16384 floats = 4096 float4
    float4* dst = reinterpret_cast<float4*>(out + 8192 + (size_t)b * 16384);
    const float4* src = reinterpret_cast<const float4*>(sout);
    for (int i = t; i < 4096; i += 256) dst[i] = src[i];
}

// ---------------- launch ----------------
extern "C" void kernel_launch(void* const* d_in, const int* in_sizes, int n_in,
                              void* d_out, int out_size) {
    const float* x  = (const float*)d_in[0];   // (128, 2592, 16)
    const float* W  = (const float*)d_in[1];   // (1, 2592, 1, 64, 16)
    const float* cw = (const float*)d_in[2];   // (32, 64, 2, 2)
    const float* cb = (const float*)d_in[3];   // (64,)
    float* out = (float*)d_out;                // 8192 (v_j) + 2097152 (out_img)

    cudaFuncSetAttribute(k6_out, cudaFuncAttributeMaxDynamicSharedMemorySize, K6_SMEM);

    kzero<<<32, 256>>>();
    k1_uhat<<<648, 256>>>(x, W);          // u_hat(fp16) + S0 + nrm2
    k_apass<<<1296, 256>>>(0);            // b1 = mean_b <u_hat, squash(S0/N)>
    k_spass<<<1296, 256>>>(0);            // c1 = softmax(b1) (per-CTA); s1 = sum c1*u_hat
    k_apass<<<1296, 256>>>(1);            // b2 = b1 + mean_b <u_hat, squash(s1)>
    k_spass<<<1296, 256>>>(1);            // c2; s2; export c2
    k6_out<<<160, 256, K6_SMEM>>>(cw, cb, out);  // v_j + ConvT (1 CTA per b)
}

// round 15
// speedup vs baseline: 1.2055x; 1.0188x over previous
#include <cuda_runtime.h>
#include <cuda_fp16.h>
#include <math.h>

#define NN 2592
#define BB 128
#define LL 64
#define CC 16
#define CHO 64

// ---------------- scratch (device globals; no allocation) ----------------
__device__ __half g_uhatH[(size_t)NN * BB * LL]; // [n][b][l]  ~42.5 MB fp16
__device__ float g_S0[BB * LL];                  // sum_n u_hat (exact fp32)
__device__ float g_s1[BB * LL];
__device__ float g_s2[BB * LL];
__device__ float g_b1[NN];
__device__ float g_b2[NN];
__device__ float g_c2[NN];
__device__ float g_nrm2[(size_t)NN * BB];        // [n][b] : sum_l u_hat^2 (exact fp32)

struct alignas(8) h4pack { __half2 a, b; };

__device__ __forceinline__ float squashf(float s) {
    float sq = s * s;
    return s * fabsf(s) / (1.0f + sq);   // == sq*s/((1+sq)*sqrt(sq))
}

__device__ __forceinline__ void red_add_v4(float* p, float a, float b, float c, float d) {
    asm volatile("red.global.add.v4.f32 [%0], {%1, %2, %3, %4};"
                 :: "l"(p), "f"(a), "f"(b), "f"(c), "f"(d) : "memory");
}

// ---------------- K0: zero accumulators ----------------
__global__ void kzero() {
    int i = blockIdx.x * 256 + threadIdx.x;
    if (i < BB * LL) { g_S0[i] = 0.f; g_s1[i] = 0.f; g_s2[i] = 0.f; }
    if (i < NN) { g_b1[i] = 0.f; g_b2[i] = 0.f; }
}

// ---------------- K1: u_hat(fp16) + S0 + nrm2 (R6 proven body) ----------------
__global__ void __launch_bounds__(256) k1_uhat(const float* __restrict__ x,
                                               const float* __restrict__ W) {
    __shared__ float xs[CC][BB];
    __shared__ float Ws[CC][LL];
    __shared__ float ps[CC][BB + 1];

    int t = threadIdx.x;
    int n0 = blockIdx.x * 4;
    int bg = t >> 4, lq = t & 15;
    int bbase = bg * 8;

    float s_acc[8][4];
#pragma unroll
    for (int i = 0; i < 8; i++)
#pragma unroll
        for (int j = 0; j < 4; j++) s_acc[i][j] = 0.f;

#pragma unroll 1
    for (int nn = 0; nn < 4; nn++) {
        int n = n0 + nn;
        {
            int b = t & 127, half = t >> 7;
            const float4* xp = reinterpret_cast<const float4*>(x + ((size_t)b * NN + n) * CC) + half * 2;
            float4 a = xp[0], c4 = xp[1];
            int cb = half * 8;
            xs[cb + 0][b] = a.x;  xs[cb + 1][b] = a.y;  xs[cb + 2][b] = a.z;  xs[cb + 3][b] = a.w;
            xs[cb + 4][b] = c4.x; xs[cb + 5][b] = c4.y; xs[cb + 6][b] = c4.z; xs[cb + 7][b] = c4.w;
        }
        {
            int l = t & 63, cq = t >> 6;
            const float4* wp = reinterpret_cast<const float4*>(W + ((size_t)n * LL + l) * CC + cq * 4);
            float4 a = wp[0];
            Ws[cq * 4 + 0][l] = a.x; Ws[cq * 4 + 1][l] = a.y;
            Ws[cq * 4 + 2][l] = a.z; Ws[cq * 4 + 3][l] = a.w;
        }
        __syncthreads();

        float acc[8][4];
#pragma unroll
        for (int i = 0; i < 8; i++)
#pragma unroll
            for (int j = 0; j < 4; j++) acc[i][j] = 0.f;

#pragma unroll
        for (int c = 0; c < CC; c++) {
            float4 xa = *reinterpret_cast<const float4*>(&xs[c][bbase]);
            float4 xb = *reinterpret_cast<const float4*>(&xs[c][bbase + 4]);
            float4 wv = *reinterpret_cast<const float4*>(&Ws[c][lq * 4]);
            float xr[8] = {xa.x, xa.y, xa.z, xa.w, xb.x, xb.y, xb.z, xb.w};
            float wr[4] = {wv.x, wv.y, wv.z, wv.w};
#pragma unroll
            for (int i = 0; i < 8; i++)
#pragma unroll
                for (int j = 0; j < 4; j++) acc[i][j] += xr[i] * wr[j];
        }

        __half* ub = g_uhatH + (size_t)n * BB * LL;
#pragma unroll
        for (int i = 0; i < 8; i++) {
            int b = bbase + i;
            h4pack pk;
            pk.a = __floats2half2_rn(acc[i][0], acc[i][1]);
            pk.b = __floats2half2_rn(acc[i][2], acc[i][3]);
            *reinterpret_cast<h4pack*>(ub + b * LL + lq * 4) = pk;
            ps[lq][b] = acc[i][0] * acc[i][0] + acc[i][1] * acc[i][1] +
                        acc[i][2] * acc[i][2] + acc[i][3] * acc[i][3];
            s_acc[i][0] += acc[i][0]; s_acc[i][1] += acc[i][1];
            s_acc[i][2] += acc[i][2]; s_acc[i][3] += acc[i][3];
        }
        __syncthreads();
        if (t < BB) {
            float nr = 0.f;
#pragma unroll
            for (int q = 0; q < 16; q++) nr += ps[q][t];
            g_nrm2[(size_t)n * BB + t] = nr;
        }
        __syncthreads();
    }

#pragma unroll
    for (int i = 0; i < 8; i++)
        red_add_v4(&g_S0[(bbase + i) * LL + lq * 4],
                   s_acc[i][0], s_acc[i][1], s_acc[i][2], s_acc[i][3]);
}

// ---------------- a-pass (R6 body, unchanged) ----------------
// grid 1296 = 324 n-tiles (8 n) x 4 b-tiles (32 b). warp w handles n0+w over 32 b.
__global__ void __launch_bounds__(256) k_apass(int mode) {
    const float* sIn = (mode == 0) ? g_S0 : g_s1;
    float sscale = (mode == 0) ? (1.0f / NN) : 1.0f;
    float* bOut = (mode == 0) ? g_b1 : g_b2;

    __shared__ float vs[32 * LL];   // 8 KB
    int t = threadIdx.x;
    int nt = blockIdx.x >> 2, bq = blockIdx.x & 3;
    int b0 = bq * 32;

    {
        const float4* sp = reinterpret_cast<const float4*>(sIn) + b0 * (LL / 4);
        float4* vp4 = reinterpret_cast<float4*>(vs);
        for (int i = t; i < 32 * LL / 4; i += 256) {
            float4 a = sp[i];
            vp4[i] = make_float4(squashf(a.x * sscale), squashf(a.y * sscale),
                                 squashf(a.z * sscale), squashf(a.w * sscale));
        }
    }
    __syncthreads();

    int w = t >> 5, lane = t & 31;
    int n = nt * 8 + w;
    const __half2* up = reinterpret_cast<const __half2*>(g_uhatH + ((size_t)n * BB + b0) * LL) + lane;
    const float2* vp = reinterpret_cast<const float2*>(vs) + lane;
    float acc = 0.f;
#pragma unroll 8
    for (int b = 0; b < 32; b++) {
        float2 u = __half22float2(up[b * 32]);
        float2 vv = vp[b * 32];
        acc += u.x * vv.x + u.y * vv.y;
    }
#pragma unroll
    for (int off = 16; off; off >>= 1) acc += __shfl_xor_sync(0xffffffffu, acc, off);
    if (lane == 0) {
        acc *= (1.0f / BB);
        if (mode == 1 && bq == 0) acc += g_b1[n];   // b2 = b1 + mean
        atomicAdd(&bOut[n], acc);
    }
}

// ---------------- s-pass: 512 threads, 8n x 64b tiles, single-pass softmax ----------------
// grid 648 = 324 n-tiles x 2 b-tiles. Softmax denom WITHOUT max-sub (b-logits are O(1):
// |v|<=0.5 elementwise => agreements bounded; exp() safe, algebra identical).
__global__ void __launch_bounds__(512) k_spass(int mode) {
    const float* bIn = (mode == 0) ? g_b1 : g_b2;
    float* sOut = (mode == 0) ? g_s1 : g_s2;

    __shared__ float wredB[16];
    __shared__ float cs[8];
    int t = threadIdx.x, lane = t & 31, wid = t >> 5;
    int nt = blockIdx.x >> 1, bq = blockIdx.x & 1;
    int n0 = nt * 8, b0 = bq * 64;

    // denom = sum exp(b)  (one pass, float4 loads, warp shuffles)
    const float4* b4 = reinterpret_cast<const float4*>(bIn);
    float sm = 0.f;
    for (int i = t; i < NN / 4; i += 512) {
        float4 v = b4[i];
        sm += __expf(v.x) + __expf(v.y) + __expf(v.z) + __expf(v.w);
    }
#pragma unroll
    for (int off = 16; off; off >>= 1) sm += __shfl_xor_sync(0xffffffffu, sm, off);
    if (lane == 0) wredB[wid] = sm;
    __syncthreads();
    float den = 0.f;
#pragma unroll
    for (int q = 0; q < 16; q++) den += wredB[q];
    float inv = 1.0f / den;

    if (t < 8) {
        float c = __expf(bIn[n0 + t]) * inv;
        cs[t] = c;
        if (mode == 1 && bq == 0) g_c2[n0 + t] = c;
    }
    __syncthreads();

    // body: thread -> (bl = t>>3 in [0,64), l4 = t&7): one uint4 (8 fp16) per n
    int bl = t >> 3, l4 = t & 7;
    float a0 = 0.f, a1 = 0.f, a2 = 0.f, a3 = 0.f;
    float a4 = 0.f, a5 = 0.f, a6 = 0.f, a7 = 0.f;
#pragma unroll
    for (int nn = 0; nn < 8; nn++) {
        float cv = cs[nn];
        const uint4* p = reinterpret_cast<const uint4*>(
            g_uhatH + ((size_t)(n0 + nn) * BB + b0 + bl) * LL);
        uint4 q = p[l4];
        float2 f0 = __half22float2(*reinterpret_cast<const __half2*>(&q.x));
        float2 f1 = __half22float2(*reinterpret_cast<const __half2*>(&q.y));
        float2 f2 = __half22float2(*reinterpret_cast<const __half2*>(&q.z));
        float2 f3 = __half22float2(*reinterpret_cast<const __half2*>(&q.w));
        a0 += cv * f0.x; a1 += cv * f0.y; a2 += cv * f1.x; a3 += cv * f1.y;
        a4 += cv * f2.x; a5 += cv * f2.y; a6 += cv * f3.x; a7 += cv * f3.y;
    }
    float* dst = sOut + (b0 + bl) * LL + l4 * 8;
    red_add_v4(dst, a0, a1, a2, a3);
    red_add_v4(dst + 4, a4, a5, a6, a7);
}

// ---------------- K6 (R14 rebuilt conv, unchanged) ----------------
#define K6_UP 85
#define K6_SMEM ((4 * 32 * 64 + 32 * K6_UP + 16384) * 4)
__global__ void __launch_bounds__(256) k6_out(const float* __restrict__ cw,
                                              const float* __restrict__ cb,
                                              float* __restrict__ out) {
    int t = threadIdx.x;
    if (blockIdx.x >= BB) {
        int idx = (blockIdx.x - BB) * 256 + t;   // 32*256 = 8192
        out[idx] = squashf(g_s2[idx]);
        return;
    }
    extern __shared__ float smem[];
    float* sw = smem;                    // [k][ic][oc], k = kh*2+kw
    float* sun = smem + 4 * 32 * 64;     // [ic][85]
    float* sout = sun + 32 * K6_UP;      // [oc][oh][ow]

    int b = blockIdx.x;

    for (int i = t; i < 8192; i += 256) {
        int oc = i & 63, ic = (i >> 6) & 31, k = i >> 11;
        sw[i] = cw[ic * 256 + oc * 4 + k];
    }
    for (int i = t; i < NN; i += 256) {
        int ic = i / 81, r = i - ic * 81;
        sun[ic * K6_UP + r] = g_c2[i] * sqrtf(g_nrm2[(size_t)i * BB + b]);
    }
    __syncthreads();

    int quad = t >> 4, g = t & 15;
    int ph = (g >> 3) & 1, pw = (g >> 2) & 1, qr = g & 3;
    int kidx = (1 - ph) * 2 + (1 - pw);
    const float* swk = sw + kidx * 32 * 64 + quad * 4;
    int row0 = (2 * qr + 0 + ph) * 9 + pw;
    int row1 = (2 * qr + 1 + ph) * 9 + pw;

    float acc[16][4];
#pragma unroll
    for (int p = 0; p < 16; p++)
#pragma unroll
        for (int j = 0; j < 4; j++) acc[p][j] = 0.f;

#pragma unroll 4
    for (int ic = 0; ic < 32; ic++) {
        float4 w4 = *reinterpret_cast<const float4*>(swk + ic * 64);
        const float* ur = sun + ic * K6_UP;
#pragma unroll
        for (int e = 0; e < 8; e++) {
            float u0 = ur[row0 + e];
            float u1 = ur[row1 + e];
            acc[e][0] += u0 * w4.x; acc[e][1] += u0 * w4.y;
            acc[e][2] += u0 * w4.z; acc[e][3] += u0 * w4.w;
            acc[8 + e][0] += u1 * w4.x; acc[8 + e][1] += u1 * w4.y;
            acc[8 + e][2] += u1 * w4.z; acc[8 + e][3] += u1 * w4.w;
        }
    }

    float4 bias4 = *reinterpret_cast<const float4*>(cb + quad * 4);
    float bb[4] = {bias4.x, bias4.y, bias4.z, bias4.w};
#pragma unroll
    for (int ar = 0; ar < 2; ar++) {
        int oh = 4 * qr + 2 * ar + ph;
#pragma unroll
        for (int e = 0; e < 8; e++) {
            int ow = 2 * e + pw;
#pragma unroll
            for (int j = 0; j < 4; j++)
                sout[((quad * 4 + j) * 16 + oh) * 16 + ow] = acc[ar * 8 + e][j] + bb[j];
        }
    }
    __syncthreads();

    float4* dst = reinterpret_cast<float4*>(out + 8192 + (size_t)b * 16384);
    const float4* src = reinterpret_cast<const float4*>(sout);
    for (int i = t; i < 4096; i += 256) dst[i] = src[i];
}

// ---------------- launch ----------------
extern "C" void kernel_launch(void* const* d_in, const int* in_sizes, int n_in,
                              void* d_out, int out_size) {
    const float* x  = (const float*)d_in[0];   // (128, 2592, 16)
    const float* W  = (const float*)d_in[1];   // (1, 2592, 1, 64, 16)
    const float* cw = (const float*)d_in[2];   // (32, 64, 2, 2)
    const float* cb = (const float*)d_in[3];   // (64,)
    float* out = (float*)d_out;                // 8192 (v_j) + 2097152 (out_img)

    cudaFuncSetAttribute(k6_out, cudaFuncAttributeMaxDynamicSharedMemorySize, K6_SMEM);

    kzero<<<32, 256>>>();
    k1_uhat<<<648, 256>>>(x, W);          // u_hat(fp16) + S0 + nrm2
    k_apass<<<1296, 256>>>(0);            // b1 = mean_b <u_hat, squash(S0/N)>
    k_spass<<<648, 512>>>(0);             // c1 = softmax(b1); s1 = sum c1*u_hat
    k_apass<<<1296, 256>>>(1);            // b2 = b1 + mean_b <u_hat, squash(s1)>
    k_spass<<<648, 512>>>(1);             // c2; s2; export c2
    k6_out<<<160, 256, K6_SMEM>>>(cw, cb, out);  // v_j + ConvT (1 CTA per b)
}